// round 2
// baseline (speedup 1.0000x reference)
#include <cuda_runtime.h>
#include <cuda_bf16.h>
#include <cstdint>

#define BSZ 128
#define DIM 1024
#define NCLS 32768
#define INV_TAU 20.0f
#define THRESH 20.0f

// Scratch (device globals: no allocations allowed). alignas(16) so vector
// loads/stores against them are legal.
__device__ alignas(16) float g_scores[BSZ * NCLS];          // 16 MB
__device__ alignas(16) __nv_bfloat16 g_abf[BSZ * DIM];      // 256 KB
__device__ alignas(16) float g_lossb[BSZ];

__device__ __forceinline__ unsigned su32(const void* p) {
    return (unsigned)__cvta_generic_to_shared(p);
}

__device__ __forceinline__ void mma_bf16(float* c, const uint32_t* a, const uint32_t* b) {
    asm volatile(
        "mma.sync.aligned.m16n8k16.row.col.f32.bf16.bf16.f32 "
        "{%0,%1,%2,%3}, {%4,%5,%6,%7}, {%8,%9}, {%0,%1,%2,%3};\n"
        : "+f"(c[0]), "+f"(c[1]), "+f"(c[2]), "+f"(c[3])
        : "r"(a[0]), "r"(a[1]), "r"(a[2]), "r"(a[3]), "r"(b[0]), "r"(b[1]));
}

// ---------------------------------------------------------------------------
// K0: convert inputs to bf16 once
// ---------------------------------------------------------------------------
__global__ void convert_inputs_kernel(const float* __restrict__ in) {
    int i = blockIdx.x * blockDim.x + threadIdx.x;
    if (i < BSZ * DIM) g_abf[i] = __float2bfloat16(in[i]);
}

// ---------------------------------------------------------------------------
// K1: GEMM (scores = inputs @ em^T * 20) fused with em -> out_em copy.
// Tile: BM=128 (all batches) x BN=128 classes, BK=32. 256 threads / block,
// 8 warps in 2x4 (M x N), each warp 64x32 via m16n8k16 bf16 mma.
// NOTE: out_em base is misaligned (d_out + 129 floats, 4 mod 16 bytes), so
// all accesses to out_em are scalar 32-bit, arranged fully coalesced.
// ---------------------------------------------------------------------------
#define BM 128
#define BN 128
#define BK 32
#define PADK 40   // 80B row stride: conflict-free for ldmatrix

__global__ __launch_bounds__(256) void gemm_kernel(const float* __restrict__ em,
                                                   float* __restrict__ out_em) {
    __shared__ __nv_bfloat16 sA[BM * PADK];
    __shared__ __nv_bfloat16 sB[BN * PADK];

    const int tid = threadIdx.x;
    const int warp = tid >> 5;
    const int lane = tid & 31;
    const int warpM = warp >> 2;  // 0..1
    const int warpN = warp & 3;   // 0..3
    const int cBase = blockIdx.x * BN;

    float acc[4][4][4];
#pragma unroll
    for (int i = 0; i < 4; i++)
#pragma unroll
        for (int j = 0; j < 4; j++)
#pragma unroll
            for (int k = 0; k < 4; k++) acc[i][j][k] = 0.0f;

    for (int k0 = 0; k0 < DIM; k0 += BK) {
        // ---- load A tile (bf16 inputs): 128 x 32, 512 chunks of 8 bf16 ----
#pragma unroll
        for (int it = 0; it < 2; it++) {
            int idx = tid + it * 256;      // 0..511
            int row = idx >> 2;            // 4 chunks per row
            int ck = (idx & 3) * 8;
            uint4 v = *reinterpret_cast<const uint4*>(&g_abf[row * DIM + k0 + ck]);
            uint2* dst = reinterpret_cast<uint2*>(&sA[row * PADK + ck]);
            dst[0] = make_uint2(v.x, v.y);
            dst[1] = make_uint2(v.z, v.w);
        }
        // ---- load B tile (fp32 em) scalar, fused copy to out_em, bf16 to smem
#pragma unroll
        for (int it = 0; it < 4; it++) {
            int idx = tid + it * 256;      // 0..1023
            int row = idx >> 3;            // 8 threads per row
            int l8 = idx & 7;
            size_t base = (size_t)(cBase + row) * DIM + k0;
#pragma unroll
            for (int q = 0; q < 4; q++) {
                int c = l8 + q * 8;        // lanes cover 32 contiguous floats
                float v = em[base + c];
                out_em[base + c] = v;      // fused copy (scalar, coalesced)
                sB[row * PADK + c] = __float2bfloat16(v);
            }
        }
        __syncthreads();

        // ---- MMA over 2 k-steps of 16 ----
#pragma unroll
        for (int ks = 0; ks < BK; ks += 16) {
            uint32_t afr[4][4];
            {
                int r = lane & 15;
                int c8 = (lane >> 4) * 8;
#pragma unroll
                for (int i = 0; i < 4; i++) {
                    unsigned addr = su32(&sA[(warpM * 64 + i * 16 + r) * PADK + ks + c8]);
                    asm volatile(
                        "ldmatrix.sync.aligned.m8n8.x4.shared.b16 {%0,%1,%2,%3}, [%4];"
                        : "=r"(afr[i][0]), "=r"(afr[i][1]), "=r"(afr[i][2]), "=r"(afr[i][3])
                        : "r"(addr));
                }
            }
            uint32_t bfr[4][2];
            {
                int rb = lane & 7;
                int cb8 = ((lane >> 3) & 1) * 8;
#pragma unroll
                for (int j = 0; j < 4; j++) {
                    unsigned addr = su32(&sB[(warpN * 32 + j * 8 + rb) * PADK + ks + cb8]);
                    asm volatile(
                        "ldmatrix.sync.aligned.m8n8.x2.shared.b16 {%0,%1}, [%2];"
                        : "=r"(bfr[j][0]), "=r"(bfr[j][1])
                        : "r"(addr));
                }
            }
#pragma unroll
            for (int i = 0; i < 4; i++)
#pragma unroll
                for (int j = 0; j < 4; j++) mma_bf16(acc[i][j], afr[i], bfr[j]);
        }
        __syncthreads();
    }

    // ---- epilogue: scores = acc * 20 (g_scores is 16B-aligned: float2 ok) ----
    const int r = lane >> 2;
    const int c2 = (lane & 3) * 2;
#pragma unroll
    for (int i = 0; i < 4; i++) {
#pragma unroll
        for (int j = 0; j < 4; j++) {
            int bb = warpM * 64 + i * 16 + r;
            int cc = cBase + warpN * 32 + j * 8 + c2;
            *reinterpret_cast<float2*>(&g_scores[(size_t)bb * NCLS + cc]) =
                make_float2(acc[i][j][0] * INV_TAU, acc[i][j][1] * INV_TAU);
            *reinterpret_cast<float2*>(&g_scores[(size_t)(bb + 8) * NCLS + cc]) =
                make_float2(acc[i][j][2] * INV_TAU, acc[i][j][3] * INV_TAU);
        }
    }
}

// ---------------------------------------------------------------------------
// K2: per-sample logsumexp + adaptive-selection loss + ks. One block per b.
// ---------------------------------------------------------------------------
__global__ __launch_bounds__(256) void reduce_kernel(const int* __restrict__ targets,
                                                     float* __restrict__ out) {
    const int b = blockIdx.x;
    const float* s = &g_scores[(size_t)b * NCLS];
    const int tid = threadIdx.x;
    __shared__ float r1[8], r2[8], r3[8];
    __shared__ float bcast;

    // pass 1: max
    float m = -1e30f;
    for (int c = tid; c < NCLS; c += 256) m = fmaxf(m, s[c]);
#pragma unroll
    for (int o = 16; o; o >>= 1) m = fmaxf(m, __shfl_xor_sync(~0u, m, o));
    if ((tid & 31) == 0) r1[tid >> 5] = m;
    __syncthreads();
    if (tid == 0) {
        float mm = r1[0];
#pragma unroll
        for (int i = 1; i < 8; i++) mm = fmaxf(mm, r1[i]);
        bcast = mm;
    }
    __syncthreads();
    m = bcast;

    // pass 2: sumexp, count above threshold, sum above threshold
    float se = 0.0f, ss = 0.0f, cn = 0.0f;
    for (int c = tid; c < NCLS; c += 256) {
        float v = s[c];
        se += expf(v - m);
        if (v > THRESH) { cn += 1.0f; ss += v; }
    }
#pragma unroll
    for (int o = 16; o; o >>= 1) {
        se += __shfl_xor_sync(~0u, se, o);
        ss += __shfl_xor_sync(~0u, ss, o);
        cn += __shfl_xor_sync(~0u, cn, o);
    }
    if ((tid & 31) == 0) { r1[tid >> 5] = se; r2[tid >> 5] = ss; r3[tid >> 5] = cn; }
    __syncthreads();
    if (tid == 0) {
        float tse = 0.0f, tss = 0.0f, tcn = 0.0f;
#pragma unroll
        for (int i = 0; i < 8; i++) { tse += r1[i]; tss += r2[i]; tcn += r3[i]; }
        float st = s[targets[b]];
        float lse = m + logf(tse);
        float logpt = st - lse;
        int n = (int)(tcn + 0.5f);
        float loss;
        if (n > 1) {
            float kk = 1.0f / ((float)n * logf((float)n));
            int ta = (st > THRESH) ? 1 : 0;
            float extra = kk * ((tss - (ta ? st : 0.0f)) - (float)(n - ta) * lse);
            loss = -(extra + logpt);
        } else {
            loss = -logpt;
        }
        g_lossb[b] = loss;
        out[1 + b] = tcn;  // ks
    }
}

// ---------------------------------------------------------------------------
// K3: deterministic mean of per-sample losses -> out[0]
// ---------------------------------------------------------------------------
__global__ void finalize_kernel(float* __restrict__ out) {
    __shared__ float sh[BSZ];
    sh[threadIdx.x] = g_lossb[threadIdx.x];
    __syncthreads();
    if (threadIdx.x == 0) {
        float acc = 0.0f;
        for (int i = 0; i < BSZ; i++) acc += sh[i];
        out[0] = acc / (float)BSZ;
    }
}

// ---------------------------------------------------------------------------
// K4: EMA scatter with renorm, preserving sequential scan semantics.
// One block per sample; non-head blocks (duplicate target seen earlier) exit;
// head block processes its full chain in order.
// ---------------------------------------------------------------------------
__global__ __launch_bounds__(1024) void scatter_kernel(const float* __restrict__ inputs,
                                                       const int* __restrict__ targets,
                                                       const int* __restrict__ epoch,
                                                       float* __restrict__ out_em) {
    const int b = blockIdx.x;
    const int y = targets[b];
    for (int j = 0; j < b; j++)
        if (targets[j] == y) return;  // uniform exit: not the chain head

    const float mu = fminf(0.4f / 60.0f * (float)(epoch[0] + 1), 1.0f);
    const int t = threadIdx.x;
    __shared__ float red[32];

    float row = out_em[(size_t)y * DIM + t];
    for (int j = b; j < BSZ; j++) {
        if (targets[j] != y) continue;  // uniform across block
        float v = mu * row + (1.0f - mu) * inputs[(size_t)j * DIM + t];
        float sq = v * v;
#pragma unroll
        for (int o = 16; o; o >>= 1) sq += __shfl_xor_sync(~0u, sq, o);
        if ((t & 31) == 0) red[t >> 5] = sq;
        __syncthreads();
        if (t < 32) {
            float x = red[t];
#pragma unroll
            for (int o = 16; o; o >>= 1) x += __shfl_xor_sync(~0u, x, o);
            if (t == 0) red[0] = x;
        }
        __syncthreads();
        row = v * rsqrtf(red[0]);
        __syncthreads();  // red reused next chain step
    }
    out_em[(size_t)y * DIM + t] = row;
}

// ---------------------------------------------------------------------------
// Entry point. Output layout (float32): [loss(1), ks(128), new_em(32768*1024)]
// ---------------------------------------------------------------------------
extern "C" void kernel_launch(void* const* d_in, const int* in_sizes, int n_in,
                              void* d_out, int out_size) {
    const float* inputs = (const float*)d_in[0];
    const float* em = (const float*)d_in[1];
    const int* targets = (const int*)d_in[2];
    const int* epoch = (const int*)d_in[3];
    float* out = (float*)d_out;
    float* out_em = out + 1 + BSZ;

    convert_inputs_kernel<<<512, 256>>>(inputs);
    gemm_kernel<<<NCLS / BN, 256>>>(em, out_em);
    reduce_kernel<<<BSZ, 256>>>(targets, out);
    finalize_kernel<<<1, BSZ>>>(out);
    scatter_kernel<<<BSZ, 1024>>>(inputs, targets, epoch, out_em);
}

// round 3
// speedup vs baseline: 1.1035x; 1.1035x over previous
#include <cuda_runtime.h>
#include <cuda_bf16.h>
#include <cstdint>

#define BSZ 128
#define DIM 1024
#define NCLS 32768
#define INV_TAU 20.0f
#define THRESH 20.0f
#define NBLK (NCLS / 128)   // 256 gemm blocks

// Scratch (device globals: no allocations allowed)
__device__ alignas(16) __nv_bfloat16 g_abf[BSZ * DIM];  // bf16 inputs
__device__ alignas(16) float g_pse[BSZ * NBLK];         // partial sumexp(s-20)
__device__ alignas(16) float g_pcn[BSZ * NBLK];         // partial count > 20
__device__ alignas(16) float g_pss[BSZ * NBLK];         // partial sum of s > 20
__device__ alignas(16) float g_st[BSZ];                 // s[target[b]]
__device__ alignas(16) float g_lossb[BSZ];

__device__ __forceinline__ unsigned su32(const void* p) {
    return (unsigned)__cvta_generic_to_shared(p);
}

__device__ __forceinline__ void mma_bf16(float* c, const uint32_t* a, const uint32_t* b) {
    asm volatile(
        "mma.sync.aligned.m16n8k16.row.col.f32.bf16.bf16.f32 "
        "{%0,%1,%2,%3}, {%4,%5,%6,%7}, {%8,%9}, {%0,%1,%2,%3};\n"
        : "+f"(c[0]), "+f"(c[1]), "+f"(c[2]), "+f"(c[3])
        : "r"(a[0]), "r"(a[1]), "r"(a[2]), "r"(a[3]), "r"(b[0]), "r"(b[1]));
}

// ---------------------------------------------------------------------------
// K0: convert inputs to bf16 once
// ---------------------------------------------------------------------------
__global__ void convert_inputs_kernel(const float* __restrict__ in) {
    int i = blockIdx.x * blockDim.x + threadIdx.x;
    if (i < BSZ * DIM) g_abf[i] = __float2bfloat16(in[i]);
}

// ---------------------------------------------------------------------------
// K1: GEMM (scores = inputs @ em^T * 20) fused with:
//   - em -> out_em copy (scalar stores: out_em base is 4 mod 16 bytes)
//   - per-tile softmax statistics (sumexp shift 20, count/sum above threshold,
//     target score capture) -> partial arrays. g_scores never materialized.
// Tile: BM=128 x BN=128 x BK=32, 256 threads, 8 warps 2x4, register
// double-buffered mainloop.
// ---------------------------------------------------------------------------
#define BM 128
#define BN 128
#define BK 32
#define PADK 40   // 80B row stride: conflict-free ldmatrix

__global__ __launch_bounds__(256, 2) void gemm_fused_kernel(const float* __restrict__ em,
                                                            float* __restrict__ out_em,
                                                            const int* __restrict__ targets) {
    __shared__ __nv_bfloat16 sA[BM * PADK];
    __shared__ __nv_bfloat16 sB[BN * PADK];
    __shared__ float sRed[3][BSZ][4];
    __shared__ int sT[BSZ];

    const int tid = threadIdx.x;
    const int warp = tid >> 5;
    const int lane = tid & 31;
    const int warpM = warp >> 2;  // 0..1
    const int warpN = warp & 3;   // 0..3
    const int cBase = blockIdx.x * BN;

    if (tid < BSZ) sT[tid] = targets[tid];

    float acc[4][4][4];
#pragma unroll
    for (int i = 0; i < 4; i++)
#pragma unroll
        for (int j = 0; j < 4; j++)
#pragma unroll
            for (int k = 0; k < 4; k++) acc[i][j][k] = 0.0f;

    // ---- prefetch registers ----
    uint4 ra[2];
    float rb[16];

    // A-chunk coords: idx in [0,512): row=idx>>2, ck=(idx&3)*8
    const int aRow0 = tid >> 2, aCk = (tid & 3) * 8;
    const int aRow1 = (tid + 256) >> 2, aCk1 = ((tid + 256) & 3) * 8;
    // B coords: idx in [0,1024): row=idx>>3, l8=idx&7, cols l8+q*8
#define LOAD_A(K0)                                                            \
    do {                                                                      \
        ra[0] = *reinterpret_cast<const uint4*>(&g_abf[aRow0 * DIM + (K0) + aCk]);  \
        ra[1] = *reinterpret_cast<const uint4*>(&g_abf[aRow1 * DIM + (K0) + aCk1]); \
    } while (0)
#define LOAD_B(K0)                                                            \
    do {                                                                      \
        _Pragma("unroll") for (int it = 0; it < 4; it++) {                    \
            int idx = tid + it * 256;                                         \
            int row = idx >> 3, l8 = idx & 7;                                 \
            size_t base = (size_t)(cBase + row) * DIM + (K0);                 \
            _Pragma("unroll") for (int q = 0; q < 4; q++)                     \
                rb[it * 4 + q] = em[base + l8 + q * 8];                       \
        }                                                                     \
    } while (0)

    LOAD_A(0);
    LOAD_B(0);

    for (int k0 = 0; k0 < DIM; k0 += BK) {
        // ---- stage registers to smem (+ fused out_em copy) ----
        {
            uint2* d0 = reinterpret_cast<uint2*>(&sA[aRow0 * PADK + aCk]);
            d0[0] = make_uint2(ra[0].x, ra[0].y);
            d0[1] = make_uint2(ra[0].z, ra[0].w);
            uint2* d1 = reinterpret_cast<uint2*>(&sA[aRow1 * PADK + aCk1]);
            d1[0] = make_uint2(ra[1].x, ra[1].y);
            d1[1] = make_uint2(ra[1].z, ra[1].w);
        }
#pragma unroll
        for (int it = 0; it < 4; it++) {
            int idx = tid + it * 256;
            int row = idx >> 3, l8 = idx & 7;
            size_t base = (size_t)(cBase + row) * DIM + k0;
#pragma unroll
            for (int q = 0; q < 4; q++) {
                float v = rb[it * 4 + q];
                out_em[base + l8 + q * 8] = v;           // coalesced scalar copy
                sB[row * PADK + l8 + q * 8] = __float2bfloat16(v);
            }
        }
        __syncthreads();

        // ---- prefetch next tile (hidden behind mma) ----
        if (k0 + BK < DIM) {
            LOAD_A(k0 + BK);
            LOAD_B(k0 + BK);
        }

        // ---- MMA over 2 k-steps of 16 ----
#pragma unroll
        for (int ks = 0; ks < BK; ks += 16) {
            uint32_t afr[4][4];
            {
                int r = lane & 15;
                int c8 = (lane >> 4) * 8;
#pragma unroll
                for (int i = 0; i < 4; i++) {
                    unsigned addr = su32(&sA[(warpM * 64 + i * 16 + r) * PADK + ks + c8]);
                    asm volatile(
                        "ldmatrix.sync.aligned.m8n8.x4.shared.b16 {%0,%1,%2,%3}, [%4];"
                        : "=r"(afr[i][0]), "=r"(afr[i][1]), "=r"(afr[i][2]), "=r"(afr[i][3])
                        : "r"(addr));
                }
            }
            uint32_t bfr[4][2];
            {
                int rb8 = lane & 7;
                int cb8 = ((lane >> 3) & 1) * 8;
#pragma unroll
                for (int j = 0; j < 4; j++) {
                    unsigned addr = su32(&sB[(warpN * 32 + j * 8 + rb8) * PADK + ks + cb8]);
                    asm volatile(
                        "ldmatrix.sync.aligned.m8n8.x2.shared.b16 {%0,%1}, [%2];"
                        : "=r"(bfr[j][0]), "=r"(bfr[j][1])
                        : "r"(addr));
                }
            }
#pragma unroll
            for (int i = 0; i < 4; i++)
#pragma unroll
                for (int j = 0; j < 4; j++) mma_bf16(acc[i][j], afr[i], bfr[j]);
        }
        __syncthreads();
    }

    // ---- fused epilogue: per-row partial statistics ----
    const int r = lane >> 2;
    const int c2 = (lane & 3) * 2;
#pragma unroll
    for (int i = 0; i < 4; i++) {
#pragma unroll
        for (int half = 0; half < 2; half++) {
            int bb = warpM * 64 + i * 16 + r + half * 8;   // global sample index
            int tgt = sT[bb];
            float se = 0.0f, cn = 0.0f, ss = 0.0f;
#pragma unroll
            for (int j = 0; j < 4; j++) {
                int cc = cBase + warpN * 32 + j * 8 + c2;
                float v0 = acc[i][j][half * 2 + 0] * INV_TAU;
                float v1 = acc[i][j][half * 2 + 1] * INV_TAU;
                se += __expf(v0 - 20.0f) + __expf(v1 - 20.0f);
                if (v0 > THRESH) { cn += 1.0f; ss += v0; }
                if (v1 > THRESH) { cn += 1.0f; ss += v1; }
                if (cc == tgt) g_st[bb] = v0;
                if (cc + 1 == tgt) g_st[bb] = v1;
            }
            // reduce over the 4 lanes sharing this row (lane = 4r + 0..3)
#pragma unroll
            for (int o = 1; o < 4; o <<= 1) {
                se += __shfl_xor_sync(~0u, se, o);
                cn += __shfl_xor_sync(~0u, cn, o);
                ss += __shfl_xor_sync(~0u, ss, o);
            }
            if ((lane & 3) == 0) {
                sRed[0][bb][warpN] = se;
                sRed[1][bb][warpN] = cn;
                sRed[2][bb][warpN] = ss;
            }
        }
    }
    __syncthreads();
    if (tid < BSZ) {
        float se = sRed[0][tid][0] + sRed[0][tid][1] + sRed[0][tid][2] + sRed[0][tid][3];
        float cn = sRed[1][tid][0] + sRed[1][tid][1] + sRed[1][tid][2] + sRed[1][tid][3];
        float ss = sRed[2][tid][0] + sRed[2][tid][1] + sRed[2][tid][2] + sRed[2][tid][3];
        g_pse[tid * NBLK + blockIdx.x] = se;
        g_pcn[tid * NBLK + blockIdx.x] = cn;
        g_pss[tid * NBLK + blockIdx.x] = ss;
    }
}

// ---------------------------------------------------------------------------
// K2: reduce partials -> per-sample loss + ks. One block per sample.
// ---------------------------------------------------------------------------
__global__ __launch_bounds__(256) void reduce_partials_kernel(float* __restrict__ out) {
    const int b = blockIdx.x;
    const int tid = threadIdx.x;
    float se = g_pse[b * NBLK + tid];
    float cn = g_pcn[b * NBLK + tid];
    float ss = g_pss[b * NBLK + tid];
#pragma unroll
    for (int o = 16; o; o >>= 1) {
        se += __shfl_xor_sync(~0u, se, o);
        cn += __shfl_xor_sync(~0u, cn, o);
        ss += __shfl_xor_sync(~0u, ss, o);
    }
    __shared__ float r1[8], r2[8], r3[8];
    if ((tid & 31) == 0) { r1[tid >> 5] = se; r2[tid >> 5] = cn; r3[tid >> 5] = ss; }
    __syncthreads();
    if (tid == 0) {
        float tse = 0.0f, tcn = 0.0f, tss = 0.0f;
#pragma unroll
        for (int i = 0; i < 8; i++) { tse += r1[i]; tcn += r2[i]; tss += r3[i]; }
        float st = g_st[b];
        float lse = 20.0f + logf(tse);
        float logpt = st - lse;
        int n = (int)(tcn + 0.5f);
        float loss;
        if (n > 1) {
            float kk = 1.0f / ((float)n * logf((float)n));
            int ta = (st > THRESH) ? 1 : 0;
            float extra = kk * ((tss - (ta ? st : 0.0f)) - (float)(n - ta) * lse);
            loss = -(extra + logpt);
        } else {
            loss = -logpt;
        }
        g_lossb[b] = loss;
        out[1 + b] = tcn;  // ks
    }
}

// ---------------------------------------------------------------------------
// K3: deterministic mean of per-sample losses -> out[0]
// ---------------------------------------------------------------------------
__global__ void finalize_kernel(float* __restrict__ out) {
    __shared__ float sh[BSZ];
    sh[threadIdx.x] = g_lossb[threadIdx.x];
    __syncthreads();
    if (threadIdx.x == 0) {
        float acc = 0.0f;
        for (int i = 0; i < BSZ; i++) acc += sh[i];
        out[0] = acc / (float)BSZ;
    }
}

// ---------------------------------------------------------------------------
// K4: EMA scatter with renorm, preserving sequential scan semantics.
// One block per sample; chain-head block processes its chain in order.
// ---------------------------------------------------------------------------
__global__ __launch_bounds__(1024) void scatter_kernel(const float* __restrict__ inputs,
                                                       const int* __restrict__ targets,
                                                       const int* __restrict__ epoch,
                                                       float* __restrict__ out_em) {
    const int b = blockIdx.x;
    const int y = targets[b];
    for (int j = 0; j < b; j++)
        if (targets[j] == y) return;  // not the chain head

    const float mu = fminf(0.4f / 60.0f * (float)(epoch[0] + 1), 1.0f);
    const int t = threadIdx.x;
    __shared__ float red[32];

    float row = out_em[(size_t)y * DIM + t];
    for (int j = b; j < BSZ; j++) {
        if (targets[j] != y) continue;  // uniform across block
        float v = mu * row + (1.0f - mu) * inputs[(size_t)j * DIM + t];
        float sq = v * v;
#pragma unroll
        for (int o = 16; o; o >>= 1) sq += __shfl_xor_sync(~0u, sq, o);
        if ((t & 31) == 0) red[t >> 5] = sq;
        __syncthreads();
        if (t < 32) {
            float x = red[t];
#pragma unroll
            for (int o = 16; o; o >>= 1) x += __shfl_xor_sync(~0u, x, o);
            if (t == 0) red[0] = x;
        }
        __syncthreads();
        row = v * rsqrtf(red[0]);
        __syncthreads();
    }
    out_em[(size_t)y * DIM + t] = row;
}

// ---------------------------------------------------------------------------
// Entry point. Output layout (float32): [loss(1), ks(128), new_em(32768*1024)]
// ---------------------------------------------------------------------------
extern "C" void kernel_launch(void* const* d_in, const int* in_sizes, int n_in,
                              void* d_out, int out_size) {
    const float* inputs = (const float*)d_in[0];
    const float* em = (const float*)d_in[1];
    const int* targets = (const int*)d_in[2];
    const int* epoch = (const int*)d_in[3];
    float* out = (float*)d_out;
    float* out_em = out + 1 + BSZ;

    convert_inputs_kernel<<<512, 256>>>(inputs);
    gemm_fused_kernel<<<NBLK, 256>>>(em, out_em, targets);
    reduce_partials_kernel<<<BSZ, 256>>>(out);
    finalize_kernel<<<1, BSZ>>>(out);
    scatter_kernel<<<BSZ, 1024>>>(inputs, targets, epoch, out_em);
}

// round 4
// speedup vs baseline: 1.2100x; 1.0964x over previous
#include <cuda_runtime.h>
#include <cuda_bf16.h>
#include <cstdint>

#define BSZ 128
#define DIM 1024
#define NCLS 32768
#define INV_TAU 20.0f
#define THRESH 20.0f
#define NBLK (NCLS / 128)   // 256 gemm blocks

// Scratch (device globals: no allocations allowed)
__device__ alignas(16) __nv_bfloat16 g_abf[BSZ * DIM];  // bf16 inputs
__device__ alignas(16) float g_pse[BSZ * NBLK];         // partial sumexp(s-20)
__device__ alignas(16) float g_pcn[BSZ * NBLK];         // partial count > 20
__device__ alignas(16) float g_pss[BSZ * NBLK];         // partial sum of s > 20
__device__ alignas(16) float g_st[BSZ];                 // s[target[b]]
__device__ alignas(16) float g_lossb[BSZ];

__device__ __forceinline__ unsigned su32(const void* p) {
    return (unsigned)__cvta_generic_to_shared(p);
}

__device__ __forceinline__ void mma_bf16(float* c, const uint32_t* a, const uint32_t* b) {
    asm volatile(
        "mma.sync.aligned.m16n8k16.row.col.f32.bf16.bf16.f32 "
        "{%0,%1,%2,%3}, {%4,%5,%6,%7}, {%8,%9}, {%0,%1,%2,%3};\n"
        : "+f"(c[0]), "+f"(c[1]), "+f"(c[2]), "+f"(c[3])
        : "r"(a[0]), "r"(a[1]), "r"(a[2]), "r"(a[3]), "r"(b[0]), "r"(b[1]));
}

__device__ __forceinline__ uint32_t pack_bf16x2(float lo, float hi) {
    return ((uint32_t)__bfloat16_as_ushort(__float2bfloat16(hi)) << 16) |
           (uint32_t)__bfloat16_as_ushort(__float2bfloat16(lo));
}

// ---------------------------------------------------------------------------
// K0: convert inputs to bf16 once
// ---------------------------------------------------------------------------
__global__ void convert_inputs_kernel(const float* __restrict__ in) {
    int i = blockIdx.x * blockDim.x + threadIdx.x;
    if (i < BSZ * DIM) g_abf[i] = __float2bfloat16(in[i]);
}

// ---------------------------------------------------------------------------
// K1: GEMM (scores = inputs @ em^T * 20) fused with em -> out_em copy and
// per-tile softmax statistics. Double-buffered smem, ONE barrier per K-iter.
// B path: LDG.128 (em) -> 4x STG.32 (out_em, base 4 mod 16) -> STS.64 bf16x2.
// ---------------------------------------------------------------------------
#define BM 128
#define BN 128
#define BK 32
#define PADK 40   // 80B row stride: conflict-light ldmatrix/STS

__global__ __launch_bounds__(256, 2) void gemm_fused_kernel(const float* __restrict__ em,
                                                            float* __restrict__ out_em,
                                                            const int* __restrict__ targets) {
    __shared__ __nv_bfloat16 sA[2][BM * PADK];
    __shared__ __nv_bfloat16 sB[2][BN * PADK];
    __shared__ float sRed[3][BSZ][4];
    __shared__ int sT[BSZ];

    const int tid = threadIdx.x;
    const int warp = tid >> 5;
    const int lane = tid & 31;
    const int warpM = warp >> 2;  // 0..1
    const int warpN = warp & 3;   // 0..3
    const int cBase = blockIdx.x * BN;

    if (tid < BSZ) sT[tid] = targets[tid];

    float acc[4][4][4];
#pragma unroll
    for (int i = 0; i < 4; i++)
#pragma unroll
        for (int j = 0; j < 4; j++)
#pragma unroll
            for (int k = 0; k < 4; k++) acc[i][j][k] = 0.0f;

    // A chunks: idx in [0,512): row=idx>>2, 8-bf16 col chunk ck=(idx&3)*8
    const int aRow0 = tid >> 2, aCk0 = (tid & 3) * 8;
    const int aRow1 = (tid + 256) >> 2, aCk1 = ((tid + 256) & 3) * 8;
    // B chunks: c = tid + it*256 in [0,1024): row=c>>3, col4=(c&7)*4 (floats)

    uint4 ra[2];
    float4 rbv[4];

#define LOAD_TILE(K0)                                                                   \
    do {                                                                                \
        ra[0] = *reinterpret_cast<const uint4*>(&g_abf[aRow0 * DIM + (K0) + aCk0]);     \
        ra[1] = *reinterpret_cast<const uint4*>(&g_abf[aRow1 * DIM + (K0) + aCk1]);     \
        _Pragma("unroll") for (int it = 0; it < 4; it++) {                              \
            int c = tid + it * 256;                                                     \
            int row = c >> 3, col4 = (c & 7) * 4;                                       \
            rbv[it] = *reinterpret_cast<const float4*>(                                 \
                &em[(size_t)(cBase + row) * DIM + (K0) + col4]);                        \
        }                                                                               \
    } while (0)

#define STAGE_TILE(BUF, K0)                                                             \
    do {                                                                                \
        *reinterpret_cast<uint4*>(&sA[BUF][aRow0 * PADK + aCk0]) = ra[0];               \
        *reinterpret_cast<uint4*>(&sA[BUF][aRow1 * PADK + aCk1]) = ra[1];               \
        _Pragma("unroll") for (int it = 0; it < 4; it++) {                              \
            int c = tid + it * 256;                                                     \
            int row = c >> 3, col4 = (c & 7) * 4;                                       \
            size_t base = (size_t)(cBase + row) * DIM + (K0) + col4;                    \
            float4 v = rbv[it];                                                         \
            out_em[base + 0] = v.x;                                                     \
            out_em[base + 1] = v.y;                                                     \
            out_em[base + 2] = v.z;                                                     \
            out_em[base + 3] = v.w;                                                     \
            *reinterpret_cast<uint2*>(&sB[BUF][row * PADK + col4]) =                    \
                make_uint2(pack_bf16x2(v.x, v.y), pack_bf16x2(v.z, v.w));               \
        }                                                                               \
    } while (0)

    LOAD_TILE(0);
    STAGE_TILE(0, 0);
    __syncthreads();

    const int NT = DIM / BK;  // 32
    for (int kt = 0; kt < NT; kt++) {
        const int cur = kt & 1;
        const bool more = (kt + 1 < NT);
        if (more) LOAD_TILE((kt + 1) * BK);

        // ---- MMA on buf[cur], hides next-tile LDGs ----
#pragma unroll
        for (int ks = 0; ks < BK; ks += 16) {
            uint32_t afr[4][4];
            {
                int r = lane & 15;
                int c8 = (lane >> 4) * 8;
#pragma unroll
                for (int i = 0; i < 4; i++) {
                    unsigned addr = su32(&sA[cur][(warpM * 64 + i * 16 + r) * PADK + ks + c8]);
                    asm volatile(
                        "ldmatrix.sync.aligned.m8n8.x4.shared.b16 {%0,%1,%2,%3}, [%4];"
                        : "=r"(afr[i][0]), "=r"(afr[i][1]), "=r"(afr[i][2]), "=r"(afr[i][3])
                        : "r"(addr));
                }
            }
            uint32_t bfr[4][2];
            {
                int rb8 = lane & 7;
                int cb8 = ((lane >> 3) & 1) * 8;
#pragma unroll
                for (int j = 0; j < 4; j++) {
                    unsigned addr = su32(&sB[cur][(warpN * 32 + j * 8 + rb8) * PADK + ks + cb8]);
                    asm volatile(
                        "ldmatrix.sync.aligned.m8n8.x2.shared.b16 {%0,%1}, [%2];"
                        : "=r"(bfr[j][0]), "=r"(bfr[j][1])
                        : "r"(addr));
                }
            }
#pragma unroll
            for (int i = 0; i < 4; i++)
#pragma unroll
                for (int j = 0; j < 4; j++) mma_bf16(acc[i][j], afr[i], bfr[j]);
        }

        if (more) STAGE_TILE(cur ^ 1, (kt + 1) * BK);
        __syncthreads();
    }

    // ---- fused epilogue: per-row partial statistics ----
    const int r = lane >> 2;
#pragma unroll
    for (int i = 0; i < 4; i++) {
#pragma unroll
        for (int half = 0; half < 2; half++) {
            int bb = warpM * 64 + i * 16 + r + half * 8;   // global sample index
            int tgt = sT[bb];
            float se = 0.0f, cn = 0.0f, ss = 0.0f;
#pragma unroll
            for (int j = 0; j < 4; j++) {
                int cc = cBase + warpN * 32 + j * 8 + (lane & 3) * 2;
                float v0 = acc[i][j][half * 2 + 0] * INV_TAU;
                float v1 = acc[i][j][half * 2 + 1] * INV_TAU;
                se += __expf(v0 - 20.0f) + __expf(v1 - 20.0f);
                if (v0 > THRESH) { cn += 1.0f; ss += v0; }
                if (v1 > THRESH) { cn += 1.0f; ss += v1; }
                if (cc == tgt) g_st[bb] = v0;
                if (cc + 1 == tgt) g_st[bb] = v1;
            }
#pragma unroll
            for (int o = 1; o < 4; o <<= 1) {
                se += __shfl_xor_sync(~0u, se, o);
                cn += __shfl_xor_sync(~0u, cn, o);
                ss += __shfl_xor_sync(~0u, ss, o);
            }
            if ((lane & 3) == 0) {
                sRed[0][bb][warpN] = se;
                sRed[1][bb][warpN] = cn;
                sRed[2][bb][warpN] = ss;
            }
        }
    }
    __syncthreads();
    if (tid < BSZ) {
        float se = sRed[0][tid][0] + sRed[0][tid][1] + sRed[0][tid][2] + sRed[0][tid][3];
        float cn = sRed[1][tid][0] + sRed[1][tid][1] + sRed[1][tid][2] + sRed[1][tid][3];
        float ss = sRed[2][tid][0] + sRed[2][tid][1] + sRed[2][tid][2] + sRed[2][tid][3];
        g_pse[tid * NBLK + blockIdx.x] = se;
        g_pcn[tid * NBLK + blockIdx.x] = cn;
        g_pss[tid * NBLK + blockIdx.x] = ss;
    }
}

// ---------------------------------------------------------------------------
// K2: reduce partials -> per-sample loss + ks. One block per sample.
// ---------------------------------------------------------------------------
__global__ __launch_bounds__(256) void reduce_partials_kernel(float* __restrict__ out) {
    const int b = blockIdx.x;
    const int tid = threadIdx.x;
    float se = g_pse[b * NBLK + tid];
    float cn = g_pcn[b * NBLK + tid];
    float ss = g_pss[b * NBLK + tid];
#pragma unroll
    for (int o = 16; o; o >>= 1) {
        se += __shfl_xor_sync(~0u, se, o);
        cn += __shfl_xor_sync(~0u, cn, o);
        ss += __shfl_xor_sync(~0u, ss, o);
    }
    __shared__ float r1[8], r2[8], r3[8];
    if ((tid & 31) == 0) { r1[tid >> 5] = se; r2[tid >> 5] = cn; r3[tid >> 5] = ss; }
    __syncthreads();
    if (tid == 0) {
        float tse = 0.0f, tcn = 0.0f, tss = 0.0f;
#pragma unroll
        for (int i = 0; i < 8; i++) { tse += r1[i]; tcn += r2[i]; tss += r3[i]; }
        float st = g_st[b];
        float lse = 20.0f + logf(tse);
        float logpt = st - lse;
        int n = (int)(tcn + 0.5f);
        float loss;
        if (n > 1) {
            float kk = 1.0f / ((float)n * logf((float)n));
            int ta = (st > THRESH) ? 1 : 0;
            float extra = kk * ((tss - (ta ? st : 0.0f)) - (float)(n - ta) * lse);
            loss = -(extra + logpt);
        } else {
            loss = -logpt;
        }
        g_lossb[b] = loss;
        out[1 + b] = tcn;  // ks
    }
}

// ---------------------------------------------------------------------------
// K3: EMA scatter with renorm, preserving sequential scan semantics.
// Block 0 additionally finalizes the loss mean (g_lossb complete: written by
// the previous launch).
// ---------------------------------------------------------------------------
__global__ __launch_bounds__(1024) void scatter_kernel(const float* __restrict__ inputs,
                                                       const int* __restrict__ targets,
                                                       const int* __restrict__ epoch,
                                                       float* __restrict__ out_em,
                                                       float* __restrict__ out) {
    const int b = blockIdx.x;
    const int y = targets[b];
    const int t = threadIdx.x;

    if (b == 0 && t == 0) {  // fused finalize
        float acc = 0.0f;
        for (int i = 0; i < BSZ; i++) acc += g_lossb[i];
        out[0] = acc / (float)BSZ;
    }

    for (int j = 0; j < b; j++)
        if (targets[j] == y) return;  // not the chain head

    const float mu = fminf(0.4f / 60.0f * (float)(epoch[0] + 1), 1.0f);
    __shared__ float red[32];

    float row = out_em[(size_t)y * DIM + t];
    for (int j = b; j < BSZ; j++) {
        if (targets[j] != y) continue;  // uniform across block
        float v = mu * row + (1.0f - mu) * inputs[(size_t)j * DIM + t];
        float sq = v * v;
#pragma unroll
        for (int o = 16; o; o >>= 1) sq += __shfl_xor_sync(~0u, sq, o);
        if ((t & 31) == 0) red[t >> 5] = sq;
        __syncthreads();
        if (t < 32) {
            float x = red[t];
#pragma unroll
            for (int o = 16; o; o >>= 1) x += __shfl_xor_sync(~0u, x, o);
            if (t == 0) red[0] = x;
        }
        __syncthreads();
        row = v * rsqrtf(red[0]);
        __syncthreads();
    }
    out_em[(size_t)y * DIM + t] = row;
}

// ---------------------------------------------------------------------------
// Entry point. Output layout (float32): [loss(1), ks(128), new_em(32768*1024)]
// ---------------------------------------------------------------------------
extern "C" void kernel_launch(void* const* d_in, const int* in_sizes, int n_in,
                              void* d_out, int out_size) {
    const float* inputs = (const float*)d_in[0];
    const float* em = (const float*)d_in[1];
    const int* targets = (const int*)d_in[2];
    const int* epoch = (const int*)d_in[3];
    float* out = (float*)d_out;
    float* out_em = out + 1 + BSZ;

    convert_inputs_kernel<<<512, 256>>>(inputs);
    gemm_fused_kernel<<<NBLK, 256>>>(em, out_em, targets);
    reduce_partials_kernel<<<BSZ, 256>>>(out);
    scatter_kernel<<<BSZ, 1024>>>(inputs, targets, epoch, out_em, out);
}